// round 3
// baseline (speedup 1.0000x reference)
#include <cuda_runtime.h>
#include <math.h>

#define Nn 1024
#define Ff 64
#define ALPHA 0.2f
#define NEG_INF -9000000000000000.0f

// scratch
__device__ float g_Wh[Nn * Ff];
__device__ float g_e1[Nn];
__device__ float g_e2[Nn];
__device__ float g_m[Nn];
__device__ float g_is[Nn];
__device__ float g_part[4][Nn * Ff];

// ---------------------------------------------------------------------------
// kA: Wh = h @ W ; e1 = Wh@a1 ; e2 = Wh@a2. grid 256 (4 rows/block).
// ---------------------------------------------------------------------------
__global__ __launch_bounds__(256) void gat_kA(const float* __restrict__ h,
                                              const float* __restrict__ W,
                                              const float* __restrict__ a) {
    __shared__ float Ws[Ff * Ff];
    __shared__ float hs[4 * Ff];
    __shared__ float a1s[Ff], a2s[Ff];
    __shared__ float es1[8], es2[8];
    int t = threadIdx.x;
    int row0 = blockIdx.x * 4;

#pragma unroll
    for (int k = 0; k < 4; k++)
        ((float4*)Ws)[t + k * 256] = ((const float4*)W)[t + k * 256];
    hs[t] = h[row0 * Ff + t];
    if (t < Ff) { a1s[t] = a[t]; a2s[t] = a[Ff + t]; }
    __syncthreads();

    int ii = t >> 6;
    int f  = t & 63;
    float acc = 0.f;
#pragma unroll
    for (int k = 0; k < Ff; k++)
        acc += hs[ii * Ff + k] * Ws[k * Ff + f];
    int row = row0 + ii;
    g_Wh[row * Ff + f] = acc;

    float p1 = acc * a1s[f];
    float p2 = acc * a2s[f];
#pragma unroll
    for (int o = 16; o; o >>= 1) {
        p1 += __shfl_xor_sync(0xffffffffu, p1, o);
        p2 += __shfl_xor_sync(0xffffffffu, p2, o);
    }
    int w = t >> 5;
    if ((t & 31) == 0) { es1[w] = p1; es2[w] = p2; }
    __syncthreads();
    if (t < 4) {
        g_e1[row0 + t] = es1[2 * t] + es1[2 * t + 1];
        g_e2[row0 + t] = es2[2 * t] + es2[2 * t + 1];
    }
}

// ---------------------------------------------------------------------------
// kB: per-row softmax stats (m, 1/sum). grid 1024 x 256 (4 cols/thread).
// ---------------------------------------------------------------------------
__global__ __launch_bounds__(256) void gat_kB(const int* __restrict__ adj) {
    int i = blockIdx.x, t = threadIdx.x;
    float e1i = g_e1[i];
    int4 av = ((const int4*)(adj + (size_t)i * Nn))[t];
    float4 e2v = ((const float4*)g_e2)[t];

    float s0 = e1i + e2v.x; s0 = (s0 > 0.f) ? s0 : ALPHA * s0; if (av.x <= 0) s0 = NEG_INF;
    float s1 = e1i + e2v.y; s1 = (s1 > 0.f) ? s1 : ALPHA * s1; if (av.y <= 0) s1 = NEG_INF;
    float s2 = e1i + e2v.z; s2 = (s2 > 0.f) ? s2 : ALPHA * s2; if (av.z <= 0) s2 = NEG_INF;
    float s3 = e1i + e2v.w; s3 = (s3 > 0.f) ? s3 : ALPHA * s3; if (av.w <= 0) s3 = NEG_INF;

    float mx = fmaxf(fmaxf(s0, s1), fmaxf(s2, s3));
#pragma unroll
    for (int o = 16; o; o >>= 1) mx = fmaxf(mx, __shfl_xor_sync(0xffffffffu, mx, o));

    __shared__ float wmax[8];
    __shared__ float wsum[8];
    __shared__ float bm;
    int w = t >> 5, l = t & 31;
    if (l == 0) wmax[w] = mx;
    __syncthreads();
    if (t < 32) {
        float v = (t < 8) ? wmax[t] : NEG_INF;
#pragma unroll
        for (int o = 4; o; o >>= 1) v = fmaxf(v, __shfl_xor_sync(0xffffffffu, v, o));
        if (t == 0) bm = v;
    }
    __syncthreads();
    float m = bm;
    float sum = __expf(s0 - m) + __expf(s1 - m) + __expf(s2 - m) + __expf(s3 - m);
#pragma unroll
    for (int o = 16; o; o >>= 1) sum += __shfl_xor_sync(0xffffffffu, sum, o);
    if (l == 0) wsum[w] = sum;
    __syncthreads();
    if (t == 0) {
        float s = 0.f;
#pragma unroll
        for (int k = 0; k < 8; k++) s += wsum[k];
        g_m[i] = m;
        g_is[i] = 1.0f / s;
    }
}

// ---------------------------------------------------------------------------
// kC: partial GEMM. grid = 128 rowgroups x 4 jsplits = 512 blocks, 256 thr.
// Block (rg, js): rows rg*8..rg*8+7, j in [js*256, js*256+256).
// p tile stored transposed ps[jj][ii] (stride 12, 16B-aligned) so the GEMM
// inner loop reads p as 2 broadcast LDS.128. Wh read directly from L2 via
// LDG.128 (each element used 8x within the register tile; no SMEM staging).
// Epilogue: 4-round tree over 16 jg splits -> g_part[js].
// ---------------------------------------------------------------------------
__global__ __launch_bounds__(256) void gat_kC(const int* __restrict__ adj) {
    __shared__ float ps[256 * 12];      // [jj][ii], stride 12
    __shared__ float4 red4[1024];       // 16KB tree buffer
    __shared__ float e1s[8], ms[8], iss[8];

    int t = threadIdx.x;
    int rg = blockIdx.x >> 2;
    int js = blockIdx.x & 3;
    int r0 = rg * 8;
    int jbase = js * 256;

    if (t < 8) {
        e1s[t] = g_e1[r0 + t];
        ms[t]  = g_m[r0 + t];
        iss[t] = g_is[r0 + t];
    }
    __syncthreads();

    // ---- p tile: thread t owns column jj = t (8 rows) ----
    {
        float e2v = g_e2[jbase + t];
        float pv[8];
#pragma unroll
        for (int ii = 0; ii < 8; ii++) {
            int av = adj[(size_t)(r0 + ii) * Nn + jbase + t];
            float sc = e1s[ii] + e2v;
            sc = (sc > 0.f) ? sc : ALPHA * sc;
            if (av <= 0) sc = NEG_INF;
            pv[ii] = __expf(sc - ms[ii]) * iss[ii];
        }
        *(float4*)&ps[t * 12]     = make_float4(pv[0], pv[1], pv[2], pv[3]);
        *(float4*)&ps[t * 12 + 4] = make_float4(pv[4], pv[5], pv[6], pv[7]);
    }
    __syncthreads();

    // ---- register-tile GEMM: thread (fi, jg), 16 j's each ----
    int fi = t & 15;
    int jg = t >> 4;
    const float4* WhL = (const float4*)(g_Wh + (size_t)jbase * Ff);

    unsigned long long acc_lo[8], acc_hi[8];
#pragma unroll
    for (int i = 0; i < 8; i++) { acc_lo[i] = 0ull; acc_hi[i] = 0ull; }

#pragma unroll 4
    for (int k = 0; k < 16; k++) {
        int j = k * 16 + jg;
        float4 wh = WhL[j * 16 + fi];
        float4 pa = *(const float4*)&ps[j * 12];
        float4 pb = *(const float4*)&ps[j * 12 + 4];
        unsigned long long wlo, whi;
        asm("mov.b64 %0,{%1,%2};" : "=l"(wlo) : "r"(__float_as_uint(wh.x)), "r"(__float_as_uint(wh.y)));
        asm("mov.b64 %0,{%1,%2};" : "=l"(whi) : "r"(__float_as_uint(wh.z)), "r"(__float_as_uint(wh.w)));
        float pr[8] = {pa.x, pa.y, pa.z, pa.w, pb.x, pb.y, pb.z, pb.w};
#pragma unroll
        for (int ii = 0; ii < 8; ii++) {
            unsigned long long pp;
            asm("mov.b64 %0,{%1,%1};" : "=l"(pp) : "r"(__float_as_uint(pr[ii])));
            asm("fma.rn.f32x2 %0,%1,%2,%0;" : "+l"(acc_lo[ii]) : "l"(pp), "l"(wlo));
            asm("fma.rn.f32x2 %0,%1,%2,%0;" : "+l"(acc_hi[ii]) : "l"(pp), "l"(whi));
        }
    }

    float af[8][4];
#pragma unroll
    for (int ii = 0; ii < 8; ii++) {
        float2 lo = *(float2*)&acc_lo[ii];
        float2 hi = *(float2*)&acc_hi[ii];
        af[ii][0] = lo.x; af[ii][1] = lo.y; af[ii][2] = hi.x; af[ii][3] = hi.y;
    }

    // ---- tree reduction over 16 jg splits ----
    __syncthreads();
#pragma unroll
    for (int sh = 8; sh >= 1; sh >>= 1) {
        if (jg >= sh && jg < 2 * sh) {
            float4* dst = &red4[((jg - sh) * 16 + fi) * 8];
#pragma unroll
            for (int ii = 0; ii < 8; ii++)
                dst[ii] = make_float4(af[ii][0], af[ii][1], af[ii][2], af[ii][3]);
        }
        __syncthreads();
        if (jg < sh) {
            const float4* sp = &red4[(jg * 16 + fi) * 8];
#pragma unroll
            for (int ii = 0; ii < 8; ii++) {
                float4 v = sp[ii];
                af[ii][0] += v.x; af[ii][1] += v.y; af[ii][2] += v.z; af[ii][3] += v.w;
            }
        }
        __syncthreads();
    }

    if (jg == 0) {
        float4* dst = (float4*)g_part[js];
#pragma unroll
        for (int ii = 0; ii < 8; ii++)
            dst[(r0 + ii) * 16 + fi] = make_float4(af[ii][0], af[ii][1], af[ii][2], af[ii][3]);
    }
}

// ---------------------------------------------------------------------------
// kD: sum 4 partials + elu. grid 64 x 256, one float4 per thread.
// ---------------------------------------------------------------------------
__global__ __launch_bounds__(256) void gat_kD(float* __restrict__ out) {
    int idx = blockIdx.x * 256 + threadIdx.x;   // 0..16383
    float4 v0 = ((const float4*)g_part[0])[idx];
    float4 v1 = ((const float4*)g_part[1])[idx];
    float4 v2 = ((const float4*)g_part[2])[idx];
    float4 v3 = ((const float4*)g_part[3])[idx];
    float4 v;
    v.x = (v0.x + v1.x) + (v2.x + v3.x);
    v.y = (v0.y + v1.y) + (v2.y + v3.y);
    v.z = (v0.z + v1.z) + (v2.z + v3.z);
    v.w = (v0.w + v1.w) + (v2.w + v3.w);
    v.x = (v.x > 0.f) ? v.x : expm1f(v.x);
    v.y = (v.y > 0.f) ? v.y : expm1f(v.y);
    v.z = (v.z > 0.f) ? v.z : expm1f(v.z);
    v.w = (v.w > 0.f) ? v.w : expm1f(v.w);
    ((float4*)out)[idx] = v;
}

// ---------------------------------------------------------------------------
extern "C" void kernel_launch(void* const* d_in, const int* in_sizes, int n_in,
                              void* d_out, int out_size) {
    const float* h   = (const float*)d_in[0];
    const int*   adj = (const int*)d_in[1];
    const float* W   = (const float*)d_in[2];
    const float* a   = (const float*)d_in[3];
    float* out = (float*)d_out;

    gat_kA<<<256, 256>>>(h, W, a);
    gat_kB<<<Nn, 256>>>(adj);
    gat_kC<<<512, 256>>>(adj);
    gat_kD<<<64, 256>>>(out);
}